// round 5
// baseline (speedup 1.0000x reference)
#include <cuda_runtime.h>

#define Nn 50000
#define Ee 600000
#define Hh 128
#define Gg 64

#define SCAN_T 512
#define SCAN_B ((Nn + SCAN_T - 1) / SCAN_T)   // 98

// ---- static scratch ----
__device__ float g_h[Nn * Hh];
__device__ float g_P[Nn * Hh];      // gemm self-loop-init output
__device__ float g_Q[Nn * Hh];      // aggregated output
__device__ float g_dinv[Nn];
__device__ int   g_deg[Nn];
__device__ int   g_aux[Nn];
__device__ int   g_rowptr[Nn + 1];
__device__ int   g_bsum[SCAN_B];
__device__ int   g_boff[SCAN_B];
__device__ int2  g_csr[Ee];
__device__ float g_pooled[Gg * Hh];

// ------------------------------------------------------------------
__global__ void init_kernel() {
    int i = blockIdx.x * blockDim.x + threadIdx.x;
    if (i < Nn) { g_deg[i] = 1; g_aux[i] = 0; }
}

__global__ void deg_kernel(const int* __restrict__ dst) {
    int e = blockIdx.x * blockDim.x + threadIdx.x;
    if (e < Ee) atomicAdd(&g_deg[dst[e]], 1);
}

// ---- scan over cnt = deg-1 to build row_ptr (also computes dinv) ----
__global__ void scanA_kernel() {
    __shared__ int ws[16];
    int tid = threadIdx.x;
    int i = blockIdx.x * SCAN_T + tid;
    int v = 0;
    if (i < Nn) {
        int d = g_deg[i];
        v = d - 1;
        g_dinv[i] = rsqrtf((float)d);
    }
#pragma unroll
    for (int o = 16; o; o >>= 1) v += __shfl_down_sync(0xffffffffu, v, o);
    if ((tid & 31) == 0) ws[tid >> 5] = v;
    __syncthreads();
    if (tid < 32) {
        int t = (tid < 16) ? ws[tid] : 0;
#pragma unroll
        for (int o = 8; o; o >>= 1) t += __shfl_down_sync(0xffffffffu, t, o);
        if (tid == 0) g_bsum[blockIdx.x] = t;
    }
}

__global__ void scanB_kernel() {
    int run = 0;
    for (int b = 0; b < SCAN_B; b++) { g_boff[b] = run; run += g_bsum[b]; }
    g_rowptr[Nn] = Ee;
}

__global__ void scanC_kernel() {
    __shared__ int wsum[16], woff[16];
    int tid = threadIdx.x;
    int lane = tid & 31, wid = tid >> 5;
    int i = blockIdx.x * SCAN_T + tid;
    int v = (i < Nn) ? (g_deg[i] - 1) : 0;
    int incl = v;
#pragma unroll
    for (int o = 1; o < 32; o <<= 1) {
        int u = __shfl_up_sync(0xffffffffu, incl, o);
        if (lane >= o) incl += u;
    }
    if (lane == 31) wsum[wid] = incl;
    __syncthreads();
    if (tid < 32) {
        int t = (tid < 16) ? wsum[tid] : 0;
        int inc = t;
#pragma unroll
        for (int o = 1; o < 16; o <<= 1) {
            int u = __shfl_up_sync(0xffffffffu, inc, o);
            if (lane >= o) inc += u;
        }
        if (tid < 16) woff[tid] = inc - t;
    }
    __syncthreads();
    if (i < Nn) g_rowptr[i] = incl - v + woff[wid] + g_boff[blockIdx.x];
}

__global__ void fill_kernel(const int* __restrict__ src, const int* __restrict__ dst) {
    int e = blockIdx.x * blockDim.x + threadIdx.x;
    if (e >= Ee) return;
    int s = src[e], d = dst[e];
    int p = g_rowptr[d] + atomicAdd(&g_aux[d], 1);
    g_csr[p] = make_int2(s, __float_as_int(g_dinv[s] * g_dinv[d]));
}

// ------------------------------------------------------------------
// GEMM: h = f(in) @ W  (f = relu(v+bprev) if apply_f)
// Packed f32x2 FMA. Tile 64x128, 256 threads, 4x8 microtile.
// smem 96KB -> 2 CTAs/SM (16 warps) for latency hiding.
// Epilogue: hout = h, accout = h * dinv^2 (self-loop).
// ------------------------------------------------------------------
__global__ void __launch_bounds__(256, 2)
gemm_kernel(const float* __restrict__ in, const float* __restrict__ W,
            const float* __restrict__ bprev, int apply_f,
            float* __restrict__ hout, float* __restrict__ accout) {
    extern __shared__ float sm[];
    float* in_s = sm;             // [64][128]  32KB
    float* W_s  = sm + 64 * Hh;   // [128][128] 64KB
    int tid = threadIdx.x;
    int r0 = blockIdx.x * 64;

    // load W (128x128): 4096 float4 / 256 threads = 16 each
#pragma unroll
    for (int i = 0; i < 16; i++) {
        int fid = tid + i * 256;
        ((float4*)W_s)[fid] = ((const float4*)W)[fid];
    }
    // load input tile (64x128): 2048 float4 / 256 = 8 each, fused bias+relu
#pragma unroll
    for (int i = 0; i < 8; i++) {
        int fid = tid + i * 256;
        int row = fid >> 5, c4 = fid & 31;
        float4 v = make_float4(0.f, 0.f, 0.f, 0.f);
        if (r0 + row < Nn) {
            v = ((const float4*)(in + (size_t)(r0 + row) * Hh))[c4];
            if (apply_f) {
                float4 b = ((const float4*)bprev)[c4];
                v.x = fmaxf(v.x + b.x, 0.f);
                v.y = fmaxf(v.y + b.y, 0.f);
                v.z = fmaxf(v.z + b.z, 0.f);
                v.w = fmaxf(v.w + b.w, 0.f);
            }
        }
        ((float4*)in_s)[fid] = v;
    }
    __syncthreads();

    int tx = tid & 15;   // col octet: cols tx*8 .. tx*8+7
    int ty = tid >> 4;   // row quad: rows ty*4 .. ty*4+3

    unsigned long long acc[4][4];
#pragma unroll
    for (int r = 0; r < 4; r++)
#pragma unroll
        for (int c = 0; c < 4; c++) acc[r][c] = 0ull;

#pragma unroll 8
    for (int k = 0; k < Hh; k++) {
        const longlong2* bp = (const longlong2*)(W_s + k * Hh + tx * 8);
        longlong2 p0 = bp[0], p1 = bp[1];
        unsigned long long b2[4] = {(unsigned long long)p0.x, (unsigned long long)p0.y,
                                    (unsigned long long)p1.x, (unsigned long long)p1.y};
#pragma unroll
        for (int r = 0; r < 4; r++) {
            float a = in_s[(ty * 4 + r) * Hh + k];
            unsigned long long a2;
            asm("mov.b64 %0, {%1, %1};" : "=l"(a2) : "f"(a));
#pragma unroll
            for (int c = 0; c < 4; c++)
                asm("fma.rn.f32x2 %0, %1, %2, %0;" : "+l"(acc[r][c]) : "l"(a2), "l"(b2[c]));
        }
    }

#pragma unroll
    for (int r = 0; r < 4; r++) {
        int row = r0 + ty * 4 + r;
        if (row < Nn) {
            float di = g_dinv[row];
            float d2 = di * di;
            float v[8];
#pragma unroll
            for (int c = 0; c < 4; c++)
                asm("mov.b64 {%0, %1}, %2;" : "=f"(v[2 * c]), "=f"(v[2 * c + 1]) : "l"(acc[r][c]));
            float4* hp = (float4*)(hout + (size_t)row * Hh + tx * 8);
            float4* ap = (float4*)(accout + (size_t)row * Hh + tx * 8);
            hp[0] = make_float4(v[0], v[1], v[2], v[3]);
            hp[1] = make_float4(v[4], v[5], v[6], v[7]);
            ap[0] = make_float4(v[0] * d2, v[1] * d2, v[2] * d2, v[3] * d2);
            ap[1] = make_float4(v[4] * d2, v[5] * d2, v[6] * d2, v[7] * d2);
        }
    }
}

// ------------------------------------------------------------------
// Aggregation: warp per node, non-atomic, 2-edge unroll for MLP.
// out[i] = init[i] + sum_{edges j->i} w_j * h[src_j]
// ------------------------------------------------------------------
__global__ void agg_kernel(const float* __restrict__ h, const float* __restrict__ init,
                           float* __restrict__ out) {
    int warp = (blockIdx.x * blockDim.x + threadIdx.x) >> 5;
    int lane = threadIdx.x & 31;
    if (warp >= Nn) return;
    int beg = g_rowptr[warp], end = g_rowptr[warp + 1];
    float4 acc = ((const float4*)(init + (size_t)warp * Hh))[lane];
    int j = beg;
    for (; j + 2 <= end; j += 2) {
        int2 e0 = g_csr[j];
        int2 e1 = g_csr[j + 1];
        float w0 = __int_as_float(e0.y);
        float w1 = __int_as_float(e1.y);
        float4 v0 = ((const float4*)(h + (size_t)e0.x * Hh))[lane];
        float4 v1 = ((const float4*)(h + (size_t)e1.x * Hh))[lane];
        acc.x = fmaf(w0, v0.x, acc.x); acc.y = fmaf(w0, v0.y, acc.y);
        acc.z = fmaf(w0, v0.z, acc.z); acc.w = fmaf(w0, v0.w, acc.w);
        acc.x = fmaf(w1, v1.x, acc.x); acc.y = fmaf(w1, v1.y, acc.y);
        acc.z = fmaf(w1, v1.z, acc.z); acc.w = fmaf(w1, v1.w, acc.w);
    }
    if (j < end) {
        int2 e0 = g_csr[j];
        float w0 = __int_as_float(e0.y);
        float4 v0 = ((const float4*)(h + (size_t)e0.x * Hh))[lane];
        acc.x = fmaf(w0, v0.x, acc.x); acc.y = fmaf(w0, v0.y, acc.y);
        acc.z = fmaf(w0, v0.z, acc.z); acc.w = fmaf(w0, v0.w, acc.w);
    }
    ((float4*)(out + (size_t)warp * Hh))[lane] = acc;
}

// ------------------------------------------------------------------
// Pool: one block per graph (batch is sorted). No atomics.
// ------------------------------------------------------------------
__device__ __forceinline__ int lower_bound_dev(const int* a, int n, int key) {
    int lo = 0, hi = n;
    while (lo < hi) {
        int mid = (lo + hi) >> 1;
        if (a[mid] < key) lo = mid + 1; else hi = mid;
    }
    return lo;
}

__global__ void pool_kernel(const int* __restrict__ batch, const float* __restrict__ acc,
                            const float* __restrict__ b3) {
    int g = blockIdx.x;
    int f = threadIdx.x;   // 128 feats
    __shared__ int s_lo, s_hi;
    if (f == 0) s_lo = lower_bound_dev(batch, Nn, g);
    if (f == 1) s_hi = lower_bound_dev(batch, Nn, g + 1);
    __syncthreads();
    int lo = s_lo, hi = s_hi;
    float b = b3[f];
    float s0 = 0.f, s1 = 0.f, s2 = 0.f, s3 = 0.f;
    int n = lo;
    for (; n + 4 <= hi; n += 4) {
        s0 += fmaxf(acc[(size_t)(n + 0) * Hh + f] + b, 0.f);
        s1 += fmaxf(acc[(size_t)(n + 1) * Hh + f] + b, 0.f);
        s2 += fmaxf(acc[(size_t)(n + 2) * Hh + f] + b, 0.f);
        s3 += fmaxf(acc[(size_t)(n + 3) * Hh + f] + b, 0.f);
    }
    for (; n < hi; n++) s0 += fmaxf(acc[(size_t)n * Hh + f] + b, 0.f);
    float s = (s0 + s1) + (s2 + s3);
    g_pooled[g * Hh + f] = s / fmaxf((float)(hi - lo), 1.f);
}

__global__ void final_kernel(const float* __restrict__ Wl, const float* __restrict__ bl,
                             float* __restrict__ out) {
    int t = threadIdx.x;  // 128
    int g = t >> 1, c = t & 1;
    float s = 0.f;
#pragma unroll 8
    for (int k = 0; k < Hh; k++)
        s += g_pooled[g * Hh + k] * Wl[k * 2 + c];
    out[g * 2 + c] = s + bl[c];
}

// ------------------------------------------------------------------
extern "C" void kernel_launch(void* const* d_in, const int* in_sizes, int n_in,
                              void* d_out, int out_size) {
    const float* x     = (const float*)d_in[0];
    const int*   ei    = (const int*)d_in[1];
    const int*   batch = (const int*)d_in[2];
    const float* W1 = (const float*)d_in[3];
    const float* b1 = (const float*)d_in[4];
    const float* W2 = (const float*)d_in[5];
    const float* b2 = (const float*)d_in[6];
    const float* W3 = (const float*)d_in[7];
    const float* b3 = (const float*)d_in[8];
    const float* Wl = (const float*)d_in[9];
    const float* bl = (const float*)d_in[10];
    float* out = (float*)d_out;

    const int* src = ei;
    const int* dst = ei + Ee;

    float *hptr, *P, *Q;
    cudaGetSymbolAddress((void**)&hptr, g_h);
    cudaGetSymbolAddress((void**)&P, g_P);
    cudaGetSymbolAddress((void**)&Q, g_Q);

    const int SMEM = (64 * Hh + Hh * Hh) * sizeof(float);   // 96 KB -> 2 CTA/SM
    cudaFuncSetAttribute(gemm_kernel, cudaFuncAttributeMaxDynamicSharedMemorySize, SMEM);

    // preprocessing (per replay, deterministic)
    init_kernel<<<(Nn + 255) / 256, 256>>>();
    deg_kernel<<<(Ee + 255) / 256, 256>>>(dst);
    scanA_kernel<<<SCAN_B, SCAN_T>>>();       // also writes dinv
    scanB_kernel<<<1, 1>>>();
    scanC_kernel<<<SCAN_B, SCAN_T>>>();
    fill_kernel<<<(Ee + 255) / 256, 256>>>(src, dst);

    int gemm_blocks = (Nn + 63) / 64;                // 782
    int agg_blocks  = (Nn * 32 + 255) / 256;         // warp per node

    // Layer 1
    gemm_kernel<<<gemm_blocks, 256, SMEM>>>(x, W1, nullptr, 0, hptr, P);
    agg_kernel<<<agg_blocks, 256>>>(hptr, P, Q);
    // Layer 2
    gemm_kernel<<<gemm_blocks, 256, SMEM>>>(Q, W2, b1, 1, hptr, P);
    agg_kernel<<<agg_blocks, 256>>>(hptr, P, Q);
    // Layer 3
    gemm_kernel<<<gemm_blocks, 256, SMEM>>>(Q, W3, b2, 1, hptr, P);
    agg_kernel<<<agg_blocks, 256>>>(hptr, P, Q);

    // Pool + head
    pool_kernel<<<Gg, Hh>>>(batch, Q, b3);
    final_kernel<<<1, 128>>>(Wl, bl, out);
}

// round 6
// speedup vs baseline: 1.1019x; 1.1019x over previous
#include <cuda_runtime.h>

#define Nn 50000
#define Ee 600000
#define Hh 128
#define Gg 64

#define SCAN_T 512
#define SCAN_B ((Nn + SCAN_T - 1) / SCAN_T)   // 98

// ---- static scratch ----
__device__ float g_h[Nn * Hh];
__device__ float g_P[Nn * Hh];      // gemm self-loop-init output
__device__ float g_Q[Nn * Hh];      // aggregated output
__device__ float g_dinv[Nn];
__device__ int   g_deg[Nn];
__device__ int   g_aux[Nn];
__device__ int   g_rowptr[Nn + 1];
__device__ int   g_bsum[SCAN_B];
__device__ int2  g_csr[Ee];
__device__ float g_pooled[Gg * Hh];

// ------------------------------------------------------------------
__global__ void init_kernel() {
    int i = blockIdx.x * blockDim.x + threadIdx.x;
    if (i < Nn) { g_deg[i] = 1; g_aux[i] = 0; }
    if (i == 0) g_rowptr[Nn] = Ee;
}

__global__ void deg_kernel(const int* __restrict__ dst) {
    int e = blockIdx.x * blockDim.x + threadIdx.x;
    if (e < Ee) atomicAdd(&g_deg[dst[e]], 1);
}

// ---- block sums of cnt = deg-1 (also computes dinv) ----
__global__ void scanA_kernel() {
    __shared__ int ws[16];
    int tid = threadIdx.x;
    int i = blockIdx.x * SCAN_T + tid;
    int v = 0;
    if (i < Nn) {
        int d = g_deg[i];
        v = d - 1;
        g_dinv[i] = rsqrtf((float)d);
    }
#pragma unroll
    for (int o = 16; o; o >>= 1) v += __shfl_down_sync(0xffffffffu, v, o);
    if ((tid & 31) == 0) ws[tid >> 5] = v;
    __syncthreads();
    if (tid < 32) {
        int t = (tid < 16) ? ws[tid] : 0;
#pragma unroll
        for (int o = 8; o; o >>= 1) t += __shfl_down_sync(0xffffffffu, t, o);
        if (tid == 0) g_bsum[blockIdx.x] = t;
    }
}

// ---- full scan: per-block prefix + fused block-offset reduce ----
__global__ void scanC_kernel() {
    __shared__ int wsum[16], woff[16];
    __shared__ int s_boff;
    int tid = threadIdx.x;
    int lane = tid & 31, wid = tid >> 5;
    int i = blockIdx.x * SCAN_T + tid;
    int v = (i < Nn) ? (g_deg[i] - 1) : 0;
    int incl = v;
#pragma unroll
    for (int o = 1; o < 32; o <<= 1) {
        int u = __shfl_up_sync(0xffffffffu, incl, o);
        if (lane >= o) incl += u;
    }
    if (lane == 31) wsum[wid] = incl;
    __syncthreads();
    if (tid < 32) {
        // exclusive scan of the 16 warp sums
        int t = (tid < 16) ? wsum[tid] : 0;
        int inc = t;
#pragma unroll
        for (int o = 1; o < 16; o <<= 1) {
            int u = __shfl_up_sync(0xffffffffu, inc, o);
            if (lane >= o) inc += u;
        }
        if (tid < 16) woff[tid] = inc - t;
        // fused: block offset = sum of g_bsum[0 .. blockIdx.x-1]
        int acc = 0;
        for (int t2 = lane; t2 < blockIdx.x; t2 += 32) acc += g_bsum[t2];
#pragma unroll
        for (int o = 16; o; o >>= 1) acc += __shfl_down_sync(0xffffffffu, acc, o);
        if (lane == 0) s_boff = acc;
    }
    __syncthreads();
    if (i < Nn) g_rowptr[i] = incl - v + woff[wid] + s_boff;
}

__global__ void fill_kernel(const int* __restrict__ src, const int* __restrict__ dst) {
    int e = blockIdx.x * blockDim.x + threadIdx.x;
    if (e >= Ee) return;
    int s = src[e], d = dst[e];
    int p = g_rowptr[d] + atomicAdd(&g_aux[d], 1);
    g_csr[p] = make_int2(s, __float_as_int(g_dinv[s] * g_dinv[d]));
}

// ------------------------------------------------------------------
// GEMM: h = f(in) @ W  (f = relu(v+bprev) if apply_f)
// Packed f32x2 FMA. Tile 128x128, 256 threads, 8x8 microtile. (R4-proven)
// Epilogue: hout = h, accout = h * dinv^2 (self-loop).
// ------------------------------------------------------------------
__global__ void __launch_bounds__(256, 1)
gemm_kernel(const float* __restrict__ in, const float* __restrict__ W,
            const float* __restrict__ bprev, int apply_f,
            float* __restrict__ hout, float* __restrict__ accout) {
    extern __shared__ float sm[];
    float* in_s = sm;              // [128][128]
    float* W_s  = sm + 128 * 128;  // [128][128]
    int tid = threadIdx.x;
    int r0 = blockIdx.x * 128;

#pragma unroll
    for (int i = 0; i < 16; i++) {
        int fid = tid + i * 256;
        ((float4*)W_s)[fid] = ((const float4*)W)[fid];
    }
#pragma unroll
    for (int i = 0; i < 16; i++) {
        int fid = tid + i * 256;
        int row = fid >> 5, c4 = fid & 31;
        float4 v = make_float4(0.f, 0.f, 0.f, 0.f);
        if (r0 + row < Nn) {
            v = ((const float4*)(in + (size_t)(r0 + row) * Hh))[c4];
            if (apply_f) {
                float4 b = ((const float4*)bprev)[c4];
                v.x = fmaxf(v.x + b.x, 0.f);
                v.y = fmaxf(v.y + b.y, 0.f);
                v.z = fmaxf(v.z + b.z, 0.f);
                v.w = fmaxf(v.w + b.w, 0.f);
            }
        }
        ((float4*)in_s)[fid] = v;
    }
    __syncthreads();

    int tx = tid & 15;   // col octet
    int ty = tid >> 4;   // row octet

    unsigned long long acc[8][4];
#pragma unroll
    for (int r = 0; r < 8; r++)
#pragma unroll
        for (int c = 0; c < 4; c++) acc[r][c] = 0ull;

#pragma unroll 8
    for (int k = 0; k < Hh; k++) {
        const longlong2* bp = (const longlong2*)(W_s + k * Hh + tx * 8);
        longlong2 p0 = bp[0], p1 = bp[1];
        unsigned long long b2[4] = {(unsigned long long)p0.x, (unsigned long long)p0.y,
                                    (unsigned long long)p1.x, (unsigned long long)p1.y};
#pragma unroll
        for (int r = 0; r < 8; r++) {
            float a = in_s[(ty * 8 + r) * Hh + k];
            unsigned long long a2;
            asm("mov.b64 %0, {%1, %1};" : "=l"(a2) : "f"(a));
#pragma unroll
            for (int c = 0; c < 4; c++)
                asm("fma.rn.f32x2 %0, %1, %2, %0;" : "+l"(acc[r][c]) : "l"(a2), "l"(b2[c]));
        }
    }

#pragma unroll
    for (int r = 0; r < 8; r++) {
        int row = r0 + ty * 8 + r;
        if (row < Nn) {
            float di = g_dinv[row];
            float d2 = di * di;
            float v[8];
#pragma unroll
            for (int c = 0; c < 4; c++)
                asm("mov.b64 {%0, %1}, %2;" : "=f"(v[2 * c]), "=f"(v[2 * c + 1]) : "l"(acc[r][c]));
            float4* hp = (float4*)(hout + (size_t)row * Hh + tx * 8);
            float4* ap = (float4*)(accout + (size_t)row * Hh + tx * 8);
            hp[0] = make_float4(v[0], v[1], v[2], v[3]);
            hp[1] = make_float4(v[4], v[5], v[6], v[7]);
            ap[0] = make_float4(v[0] * d2, v[1] * d2, v[2] * d2, v[3] * d2);
            ap[1] = make_float4(v[4] * d2, v[5] * d2, v[6] * d2, v[7] * d2);
        }
    }
}

// ------------------------------------------------------------------
// Aggregation: warp per node, non-atomic, pipelined edge fetch. (R4-proven)
// out[i] = init[i] + sum_{edges j->i} w_j * h[src_j]
// ------------------------------------------------------------------
__global__ void agg_kernel(const float* __restrict__ h, const float* __restrict__ init,
                           float* __restrict__ out) {
    int warp = (blockIdx.x * blockDim.x + threadIdx.x) >> 5;
    int lane = threadIdx.x & 31;
    if (warp >= Nn) return;
    int beg = g_rowptr[warp], end = g_rowptr[warp + 1];
    float4 acc = ((const float4*)(init + (size_t)warp * Hh))[lane];
    int2 e = make_int2(0, 0);
    if (beg < end) e = g_csr[beg];
    for (int j = beg; j < end; j++) {
        int2 cur = e;
        if (j + 1 < end) e = g_csr[j + 1];
        float w = __int_as_float(cur.y);
        float4 v = ((const float4*)(h + (size_t)cur.x * Hh))[lane];
        acc.x = fmaf(w, v.x, acc.x);
        acc.y = fmaf(w, v.y, acc.y);
        acc.z = fmaf(w, v.z, acc.z);
        acc.w = fmaf(w, v.w, acc.w);
    }
    ((float4*)(out + (size_t)warp * Hh))[lane] = acc;
}

// ------------------------------------------------------------------
// Pool: one block per graph (batch is sorted). No atomics.
// ------------------------------------------------------------------
__device__ __forceinline__ int lower_bound_dev(const int* a, int n, int key) {
    int lo = 0, hi = n;
    while (lo < hi) {
        int mid = (lo + hi) >> 1;
        if (a[mid] < key) lo = mid + 1; else hi = mid;
    }
    return lo;
}

__global__ void pool_kernel(const int* __restrict__ batch, const float* __restrict__ acc,
                            const float* __restrict__ b3) {
    int g = blockIdx.x;
    int f = threadIdx.x;   // 128 feats
    __shared__ int s_lo, s_hi;
    if (f == 0) s_lo = lower_bound_dev(batch, Nn, g);
    if (f == 1) s_hi = lower_bound_dev(batch, Nn, g + 1);
    __syncthreads();
    int lo = s_lo, hi = s_hi;
    float b = b3[f];
    float s0 = 0.f, s1 = 0.f, s2 = 0.f, s3 = 0.f;
    int n = lo;
    for (; n + 4 <= hi; n += 4) {
        s0 += fmaxf(acc[(size_t)(n + 0) * Hh + f] + b, 0.f);
        s1 += fmaxf(acc[(size_t)(n + 1) * Hh + f] + b, 0.f);
        s2 += fmaxf(acc[(size_t)(n + 2) * Hh + f] + b, 0.f);
        s3 += fmaxf(acc[(size_t)(n + 3) * Hh + f] + b, 0.f);
    }
    for (; n < hi; n++) s0 += fmaxf(acc[(size_t)n * Hh + f] + b, 0.f);
    float s = (s0 + s1) + (s2 + s3);
    g_pooled[g * Hh + f] = s / fmaxf((float)(hi - lo), 1.f);
}

__global__ void final_kernel(const float* __restrict__ Wl, const float* __restrict__ bl,
                             float* __restrict__ out) {
    int t = threadIdx.x;  // 128
    int g = t >> 1, c = t & 1;
    float s = 0.f;
#pragma unroll 8
    for (int k = 0; k < Hh; k++)
        s += g_pooled[g * Hh + k] * Wl[k * 2 + c];
    out[g * 2 + c] = s + bl[c];
}

// ------------------------------------------------------------------
extern "C" void kernel_launch(void* const* d_in, const int* in_sizes, int n_in,
                              void* d_out, int out_size) {
    const float* x     = (const float*)d_in[0];
    const int*   ei    = (const int*)d_in[1];
    const int*   batch = (const int*)d_in[2];
    const float* W1 = (const float*)d_in[3];
    const float* b1 = (const float*)d_in[4];
    const float* W2 = (const float*)d_in[5];
    const float* b2 = (const float*)d_in[6];
    const float* W3 = (const float*)d_in[7];
    const float* b3 = (const float*)d_in[8];
    const float* Wl = (const float*)d_in[9];
    const float* bl = (const float*)d_in[10];
    float* out = (float*)d_out;

    const int* src = ei;
    const int* dst = ei + Ee;

    float *hptr, *P, *Q;
    cudaGetSymbolAddress((void**)&hptr, g_h);
    cudaGetSymbolAddress((void**)&P, g_P);
    cudaGetSymbolAddress((void**)&Q, g_Q);

    const int SMEM = 2 * Hh * Hh * sizeof(float);   // 128 KB
    cudaFuncSetAttribute(gemm_kernel, cudaFuncAttributeMaxDynamicSharedMemorySize, SMEM);

    // preprocessing: 5 launches, so ncu (-s 5) captures gemm #1 next round
    init_kernel<<<(Nn + 255) / 256, 256>>>();
    deg_kernel<<<(Ee + 255) / 256, 256>>>(dst);
    scanA_kernel<<<SCAN_B, SCAN_T>>>();       // block sums + dinv
    scanC_kernel<<<SCAN_B, SCAN_T>>>();       // full scan (fused block offsets)
    fill_kernel<<<(Ee + 255) / 256, 256>>>(src, dst);

    int gemm_blocks = (Nn + 127) / 128;              // 391
    int agg_blocks  = (Nn * 32 + 255) / 256;         // warp per node

    // Layer 1
    gemm_kernel<<<gemm_blocks, 256, SMEM>>>(x, W1, nullptr, 0, hptr, P);
    agg_kernel<<<agg_blocks, 256>>>(hptr, P, Q);
    // Layer 2
    gemm_kernel<<<gemm_blocks, 256, SMEM>>>(Q, W2, b1, 1, hptr, P);
    agg_kernel<<<agg_blocks, 256>>>(hptr, P, Q);
    // Layer 3
    gemm_kernel<<<gemm_blocks, 256, SMEM>>>(Q, W3, b2, 1, hptr, P);
    agg_kernel<<<agg_blocks, 256>>>(hptr, P, Q);

    // Pool + head
    pool_kernel<<<Gg, Hh>>>(batch, Q, b3);
    final_kernel<<<1, 128>>>(Wl, bl, out);
}

// round 7
// speedup vs baseline: 1.1248x; 1.0208x over previous
#include <cuda_runtime.h>

#define Nn 50000
#define Ee 600000
#define Hh 128
#define Gg 64

#define SCAN_T 512
#define SCAN_B ((Nn + SCAN_T - 1) / SCAN_T)   // 98

// ---- static scratch ----
__device__ float g_h[Nn * Hh];
__device__ float g_P[Nn * Hh];      // gemm self-loop-init output
__device__ float g_Q[Nn * Hh];      // aggregated output
__device__ float g_dinv[Nn];
__device__ int   g_deg[Nn];         // edge-in count (no self loop)
__device__ int   g_rank[Ee];        // per-edge slot within its dst row
__device__ int   g_rowptr[Nn + 1];
__device__ int   g_bsum[SCAN_B];
__device__ int2  g_csr[Ee];
__device__ float g_pooled[Gg * Hh];

// ------------------------------------------------------------------
__global__ void init_kernel() {
    int i = blockIdx.x * blockDim.x + threadIdx.x;
    if (i < Nn) g_deg[i] = 0;
    if (i == 0) g_rowptr[Nn] = Ee;
}

// deg count; the returned old value is this edge's unique rank in its row
__global__ void deg_kernel(const int* __restrict__ dst) {
    int e = blockIdx.x * blockDim.x + threadIdx.x;
    if (e < Ee) g_rank[e] = atomicAdd(&g_deg[dst[e]], 1);
}

// ---- block sums of deg (CSR counts) + dinv = rsqrt(deg+1) ----
__global__ void scanA_kernel() {
    __shared__ int ws[16];
    int tid = threadIdx.x;
    int i = blockIdx.x * SCAN_T + tid;
    int v = 0;
    if (i < Nn) {
        int d = g_deg[i];
        v = d;
        g_dinv[i] = rsqrtf((float)(d + 1));
    }
#pragma unroll
    for (int o = 16; o; o >>= 1) v += __shfl_down_sync(0xffffffffu, v, o);
    if ((tid & 31) == 0) ws[tid >> 5] = v;
    __syncthreads();
    if (tid < 32) {
        int t = (tid < 16) ? ws[tid] : 0;
#pragma unroll
        for (int o = 8; o; o >>= 1) t += __shfl_down_sync(0xffffffffu, t, o);
        if (tid == 0) g_bsum[blockIdx.x] = t;
    }
}

// ---- full exclusive scan: per-block prefix + fused block-offset reduce ----
__global__ void scanC_kernel() {
    __shared__ int wsum[16], woff[16];
    __shared__ int s_boff;
    int tid = threadIdx.x;
    int lane = tid & 31, wid = tid >> 5;
    int i = blockIdx.x * SCAN_T + tid;
    int v = (i < Nn) ? g_deg[i] : 0;
    int incl = v;
#pragma unroll
    for (int o = 1; o < 32; o <<= 1) {
        int u = __shfl_up_sync(0xffffffffu, incl, o);
        if (lane >= o) incl += u;
    }
    if (lane == 31) wsum[wid] = incl;
    __syncthreads();
    if (tid < 32) {
        int t = (tid < 16) ? wsum[tid] : 0;
        int inc = t;
#pragma unroll
        for (int o = 1; o < 16; o <<= 1) {
            int u = __shfl_up_sync(0xffffffffu, inc, o);
            if (lane >= o) inc += u;
        }
        if (tid < 16) woff[tid] = inc - t;
        int acc = 0;
        for (int t2 = lane; t2 < blockIdx.x; t2 += 32) acc += g_bsum[t2];
#pragma unroll
        for (int o = 16; o; o >>= 1) acc += __shfl_down_sync(0xffffffffu, acc, o);
        if (lane == 0) s_boff = acc;
    }
    __syncthreads();
    if (i < Nn) g_rowptr[i] = incl - v + woff[wid] + s_boff;
}

// atomic-free CSR fill using precomputed ranks
__global__ void fill_kernel(const int* __restrict__ src, const int* __restrict__ dst) {
    int e = blockIdx.x * blockDim.x + threadIdx.x;
    if (e >= Ee) return;
    int s = src[e], d = dst[e];
    int p = g_rowptr[d] + g_rank[e];
    g_csr[p] = make_int2(s, __float_as_int(g_dinv[s] * g_dinv[d]));
}

// ------------------------------------------------------------------
// GEMM: h = f(in) @ W  (f = relu(v+bprev) if apply_f)
// Packed f32x2 FMA. Tile 128x128, 256 threads, 8x8 microtile. (R4/R6-proven)
// Epilogue: hout = h, accout = h * dinv^2 (self-loop).
// ------------------------------------------------------------------
__global__ void __launch_bounds__(256, 1)
gemm_kernel(const float* __restrict__ in, const float* __restrict__ W,
            const float* __restrict__ bprev, int apply_f,
            float* __restrict__ hout, float* __restrict__ accout) {
    extern __shared__ float sm[];
    float* in_s = sm;              // [128][128]
    float* W_s  = sm + 128 * 128;  // [128][128]
    int tid = threadIdx.x;
    int r0 = blockIdx.x * 128;

#pragma unroll
    for (int i = 0; i < 16; i++) {
        int fid = tid + i * 256;
        ((float4*)W_s)[fid] = ((const float4*)W)[fid];
    }
#pragma unroll
    for (int i = 0; i < 16; i++) {
        int fid = tid + i * 256;
        int row = fid >> 5, c4 = fid & 31;
        float4 v = make_float4(0.f, 0.f, 0.f, 0.f);
        if (r0 + row < Nn) {
            v = ((const float4*)(in + (size_t)(r0 + row) * Hh))[c4];
            if (apply_f) {
                float4 b = ((const float4*)bprev)[c4];
                v.x = fmaxf(v.x + b.x, 0.f);
                v.y = fmaxf(v.y + b.y, 0.f);
                v.z = fmaxf(v.z + b.z, 0.f);
                v.w = fmaxf(v.w + b.w, 0.f);
            }
        }
        ((float4*)in_s)[fid] = v;
    }
    __syncthreads();

    int tx = tid & 15;
    int ty = tid >> 4;

    unsigned long long acc[8][4];
#pragma unroll
    for (int r = 0; r < 8; r++)
#pragma unroll
        for (int c = 0; c < 4; c++) acc[r][c] = 0ull;

#pragma unroll 8
    for (int k = 0; k < Hh; k++) {
        const longlong2* bp = (const longlong2*)(W_s + k * Hh + tx * 8);
        longlong2 p0 = bp[0], p1 = bp[1];
        unsigned long long b2[4] = {(unsigned long long)p0.x, (unsigned long long)p0.y,
                                    (unsigned long long)p1.x, (unsigned long long)p1.y};
#pragma unroll
        for (int r = 0; r < 8; r++) {
            float a = in_s[(ty * 8 + r) * Hh + k];
            unsigned long long a2;
            asm("mov.b64 %0, {%1, %1};" : "=l"(a2) : "f"(a));
#pragma unroll
            for (int c = 0; c < 4; c++)
                asm("fma.rn.f32x2 %0, %1, %2, %0;" : "+l"(acc[r][c]) : "l"(a2), "l"(b2[c]));
        }
    }

#pragma unroll
    for (int r = 0; r < 8; r++) {
        int row = r0 + ty * 8 + r;
        if (row < Nn) {
            float di = g_dinv[row];
            float d2 = di * di;
            float v[8];
#pragma unroll
            for (int c = 0; c < 4; c++)
                asm("mov.b64 {%0, %1}, %2;" : "=f"(v[2 * c]), "=f"(v[2 * c + 1]) : "l"(acc[r][c]));
            float4* hp = (float4*)(hout + (size_t)row * Hh + tx * 8);
            float4* ap = (float4*)(accout + (size_t)row * Hh + tx * 8);
            hp[0] = make_float4(v[0], v[1], v[2], v[3]);
            hp[1] = make_float4(v[4], v[5], v[6], v[7]);
            ap[0] = make_float4(v[0] * d2, v[1] * d2, v[2] * d2, v[3] * d2);
            ap[1] = make_float4(v[4] * d2, v[5] * d2, v[6] * d2, v[7] * d2);
        }
    }
}

// ------------------------------------------------------------------
// Aggregation: warp per node, non-atomic, pipelined edge fetch. (R6-proven)
// ------------------------------------------------------------------
__global__ void agg_kernel(const float* __restrict__ h, const float* __restrict__ init,
                           float* __restrict__ out) {
    int warp = (blockIdx.x * blockDim.x + threadIdx.x) >> 5;
    int lane = threadIdx.x & 31;
    if (warp >= Nn) return;
    int beg = g_rowptr[warp], end = g_rowptr[warp + 1];
    float4 acc = ((const float4*)(init + (size_t)warp * Hh))[lane];
    int2 e = make_int2(0, 0);
    if (beg < end) e = g_csr[beg];
    for (int j = beg; j < end; j++) {
        int2 cur = e;
        if (j + 1 < end) e = g_csr[j + 1];
        float w = __int_as_float(cur.y);
        float4 v = ((const float4*)(h + (size_t)cur.x * Hh))[lane];
        acc.x = fmaf(w, v.x, acc.x);
        acc.y = fmaf(w, v.y, acc.y);
        acc.z = fmaf(w, v.z, acc.z);
        acc.w = fmaf(w, v.w, acc.w);
    }
    ((float4*)(out + (size_t)warp * Hh))[lane] = acc;
}

// ------------------------------------------------------------------
__device__ __forceinline__ int lower_bound_dev(const int* a, int n, int key) {
    int lo = 0, hi = n;
    while (lo < hi) {
        int mid = (lo + hi) >> 1;
        if (a[mid] < key) lo = mid + 1; else hi = mid;
    }
    return lo;
}

__global__ void pool_kernel(const int* __restrict__ batch, const float* __restrict__ acc,
                            const float* __restrict__ b3) {
    int g = blockIdx.x;
    int f = threadIdx.x;
    __shared__ int s_lo, s_hi;
    if (f == 0) s_lo = lower_bound_dev(batch, Nn, g);
    if (f == 1) s_hi = lower_bound_dev(batch, Nn, g + 1);
    __syncthreads();
    int lo = s_lo, hi = s_hi;
    float b = b3[f];
    float s0 = 0.f, s1 = 0.f, s2 = 0.f, s3 = 0.f;
    int n = lo;
    for (; n + 4 <= hi; n += 4) {
        s0 += fmaxf(acc[(size_t)(n + 0) * Hh + f] + b, 0.f);
        s1 += fmaxf(acc[(size_t)(n + 1) * Hh + f] + b, 0.f);
        s2 += fmaxf(acc[(size_t)(n + 2) * Hh + f] + b, 0.f);
        s3 += fmaxf(acc[(size_t)(n + 3) * Hh + f] + b, 0.f);
    }
    for (; n < hi; n++) s0 += fmaxf(acc[(size_t)n * Hh + f] + b, 0.f);
    float s = (s0 + s1) + (s2 + s3);
    g_pooled[g * Hh + f] = s / fmaxf((float)(hi - lo), 1.f);
}

__global__ void final_kernel(const float* __restrict__ Wl, const float* __restrict__ bl,
                             float* __restrict__ out) {
    int t = threadIdx.x;
    int g = t >> 1, c = t & 1;
    float s = 0.f;
#pragma unroll 8
    for (int k = 0; k < Hh; k++)
        s += g_pooled[g * Hh + k] * Wl[k * 2 + c];
    out[g * 2 + c] = s + bl[c];
}

// ------------------------------------------------------------------
extern "C" void kernel_launch(void* const* d_in, const int* in_sizes, int n_in,
                              void* d_out, int out_size) {
    const float* x     = (const float*)d_in[0];
    const int*   ei    = (const int*)d_in[1];
    const int*   batch = (const int*)d_in[2];
    const float* W1 = (const float*)d_in[3];
    const float* b1 = (const float*)d_in[4];
    const float* W2 = (const float*)d_in[5];
    const float* b2 = (const float*)d_in[6];
    const float* W3 = (const float*)d_in[7];
    const float* b3 = (const float*)d_in[8];
    const float* Wl = (const float*)d_in[9];
    const float* bl = (const float*)d_in[10];
    float* out = (float*)d_out;

    const int* src = ei;
    const int* dst = ei + Ee;

    float *hptr, *P, *Q;
    cudaGetSymbolAddress((void**)&hptr, g_h);
    cudaGetSymbolAddress((void**)&P, g_P);
    cudaGetSymbolAddress((void**)&Q, g_Q);

    const int SMEM = 2 * Hh * Hh * sizeof(float);   // 128 KB
    cudaFuncSetAttribute(gemm_kernel, cudaFuncAttributeMaxDynamicSharedMemorySize, SMEM);

    int gemm_blocks = (Nn + 127) / 128;              // 391
    int agg_blocks  = (Nn * 32 + 255) / 256;

    // #1..#3: minimal prefix so gemm1 is launch #4 (ncu captures #4)
    init_kernel<<<(Nn + 255) / 256, 256>>>();
    deg_kernel<<<(Ee + 255) / 256, 256>>>(dst);      // also writes ranks
    scanA_kernel<<<SCAN_B, SCAN_T>>>();              // block sums + dinv

    // #4: layer-1 GEMM (needs only dinv)
    gemm_kernel<<<gemm_blocks, 256, SMEM>>>(x, W1, nullptr, 0, hptr, P);

    // finish CSR build, then aggregate
    scanC_kernel<<<SCAN_B, SCAN_T>>>();
    fill_kernel<<<(Ee + 255) / 256, 256>>>(src, dst);
    agg_kernel<<<agg_blocks, 256>>>(hptr, P, Q);

    // Layer 2
    gemm_kernel<<<gemm_blocks, 256, SMEM>>>(Q, W2, b1, 1, hptr, P);
    agg_kernel<<<agg_blocks, 256>>>(hptr, P, Q);
    // Layer 3
    gemm_kernel<<<gemm_blocks, 256, SMEM>>>(Q, W3, b2, 1, hptr, P);
    agg_kernel<<<agg_blocks, 256>>>(hptr, P, Q);

    // Pool + head
    pool_kernel<<<Gg, Hh>>>(batch, Q, b3);
    final_kernel<<<1, 128>>>(Wl, bl, out);
}

// round 8
// speedup vs baseline: 1.1501x; 1.0224x over previous
#include <cuda_runtime.h>

#define Nn 50000
#define Ee 600000
#define Hh 128
#define Gg 64

#define SCAN_T 512
#define SCAN_B ((Nn + SCAN_T - 1) / SCAN_T)   // 98

// ---- static scratch ----
__device__ float g_h[Nn * Hh];
__device__ float g_P[Nn * Hh];      // gemm self-loop-init output
__device__ float g_Q[Nn * Hh];      // aggregated output
__device__ float g_dinv[Nn];
__device__ int   g_deg[Nn];         // edge-in count (no self loop)
__device__ int   g_rank[Ee];        // per-edge slot within its dst row
__device__ int   g_rowptr[Nn + 1];
__device__ int   g_bsum[SCAN_B];
__device__ int2  g_csr[Ee];
__device__ float g_pooled[Gg * Hh];

// ------------------------------------------------------------------
__global__ void init_kernel() {
    int i = blockIdx.x * blockDim.x + threadIdx.x;
    if (i < Nn) g_deg[i] = 0;
    if (i == 0) g_rowptr[Nn] = Ee;
}

// deg count; returned old value is this edge's unique rank in its row
__global__ void deg_kernel(const int* __restrict__ dst) {
    int e = blockIdx.x * blockDim.x + threadIdx.x;
    if (e < Ee) g_rank[e] = atomicAdd(&g_deg[dst[e]], 1);
}

// ---- block sums of deg (CSR counts) + dinv = rsqrt(deg+1) ----
__global__ void scanA_kernel() {
    __shared__ int ws[16];
    int tid = threadIdx.x;
    int i = blockIdx.x * SCAN_T + tid;
    int v = 0;
    if (i < Nn) {
        int d = g_deg[i];
        v = d;
        g_dinv[i] = rsqrtf((float)(d + 1));
    }
#pragma unroll
    for (int o = 16; o; o >>= 1) v += __shfl_down_sync(0xffffffffu, v, o);
    if ((tid & 31) == 0) ws[tid >> 5] = v;
    __syncthreads();
    if (tid < 32) {
        int t = (tid < 16) ? ws[tid] : 0;
#pragma unroll
        for (int o = 8; o; o >>= 1) t += __shfl_down_sync(0xffffffffu, t, o);
        if (tid == 0) g_bsum[blockIdx.x] = t;
    }
}

// ---- full exclusive scan: per-block prefix + fused block-offset reduce ----
__global__ void scanC_kernel() {
    __shared__ int wsum[16], woff[16];
    __shared__ int s_boff;
    int tid = threadIdx.x;
    int lane = tid & 31, wid = tid >> 5;
    int i = blockIdx.x * SCAN_T + tid;
    int v = (i < Nn) ? g_deg[i] : 0;
    int incl = v;
#pragma unroll
    for (int o = 1; o < 32; o <<= 1) {
        int u = __shfl_up_sync(0xffffffffu, incl, o);
        if (lane >= o) incl += u;
    }
    if (lane == 31) wsum[wid] = incl;
    __syncthreads();
    if (tid < 32) {
        int t = (tid < 16) ? wsum[tid] : 0;
        int inc = t;
#pragma unroll
        for (int o = 1; o < 16; o <<= 1) {
            int u = __shfl_up_sync(0xffffffffu, inc, o);
            if (lane >= o) inc += u;
        }
        if (tid < 16) woff[tid] = inc - t;
        int acc = 0;
        for (int t2 = lane; t2 < blockIdx.x; t2 += 32) acc += g_bsum[t2];
#pragma unroll
        for (int o = 16; o; o >>= 1) acc += __shfl_down_sync(0xffffffffu, acc, o);
        if (lane == 0) s_boff = acc;
    }
    __syncthreads();
    if (i < Nn) g_rowptr[i] = incl - v + woff[wid] + s_boff;
}

// atomic-free CSR fill using precomputed ranks
__global__ void fill_kernel(const int* __restrict__ src, const int* __restrict__ dst) {
    int e = blockIdx.x * blockDim.x + threadIdx.x;
    if (e >= Ee) return;
    int s = src[e], d = dst[e];
    int p = g_rowptr[d] + g_rank[e];
    g_csr[p] = make_int2(s, __float_as_int(g_dinv[s] * g_dinv[d]));
}

// ------------------------------------------------------------------
// GEMM: h = f(in) @ W  (f = relu(v+bprev) if apply_f)
// Packed f32x2 FMA. Tile 128x128, **512 threads**, 8x4 microtile.
// 16 warps/SM (4/SMSP) to feed the FFMA2 pipe.
// Epilogue: hout = h, accout = h * dinv^2 (self-loop).
// ------------------------------------------------------------------
__global__ void __launch_bounds__(512, 1)
gemm_kernel(const float* __restrict__ in, const float* __restrict__ W,
            const float* __restrict__ bprev, int apply_f,
            float* __restrict__ hout, float* __restrict__ accout) {
    extern __shared__ float sm[];
    float* in_s = sm;              // [128][128]
    float* W_s  = sm + 128 * 128;  // [128][128]
    int tid = threadIdx.x;
    int r0 = blockIdx.x * 128;

    // load W (128x128): 4096 float4 / 512 threads = 8 each
#pragma unroll
    for (int i = 0; i < 8; i++) {
        int fid = tid + i * 512;
        ((float4*)W_s)[fid] = ((const float4*)W)[fid];
    }
    // load input tile (128x128): 4096 float4 / 512 = 8 each, fused bias+relu
#pragma unroll
    for (int i = 0; i < 8; i++) {
        int fid = tid + i * 512;
        int row = fid >> 5, c4 = fid & 31;
        float4 v = make_float4(0.f, 0.f, 0.f, 0.f);
        if (r0 + row < Nn) {
            v = ((const float4*)(in + (size_t)(r0 + row) * Hh))[c4];
            if (apply_f) {
                float4 b = ((const float4*)bprev)[c4];
                v.x = fmaxf(v.x + b.x, 0.f);
                v.y = fmaxf(v.y + b.y, 0.f);
                v.z = fmaxf(v.z + b.z, 0.f);
                v.w = fmaxf(v.w + b.w, 0.f);
            }
        }
        ((float4*)in_s)[fid] = v;
    }
    __syncthreads();

    int tx = tid & 31;   // col quad: cols tx*4 .. tx*4+3
    int ty = tid >> 5;   // row octet: rows ty*8 .. ty*8+7 (uniform per warp -> a broadcast)

    unsigned long long acc[8][2];
#pragma unroll
    for (int r = 0; r < 8; r++) { acc[r][0] = 0ull; acc[r][1] = 0ull; }

#pragma unroll 8
    for (int k = 0; k < Hh; k++) {
        longlong2 bp = ((const longlong2*)(W_s + k * Hh + tx * 4))[0];
        unsigned long long b0 = (unsigned long long)bp.x;
        unsigned long long b1 = (unsigned long long)bp.y;
#pragma unroll
        for (int r = 0; r < 8; r++) {
            float a = in_s[(ty * 8 + r) * Hh + k];
            unsigned long long a2;
            asm("mov.b64 %0, {%1, %1};" : "=l"(a2) : "f"(a));
            asm("fma.rn.f32x2 %0, %1, %2, %0;" : "+l"(acc[r][0]) : "l"(a2), "l"(b0));
            asm("fma.rn.f32x2 %0, %1, %2, %0;" : "+l"(acc[r][1]) : "l"(a2), "l"(b1));
        }
    }

#pragma unroll
    for (int r = 0; r < 8; r++) {
        int row = r0 + ty * 8 + r;
        if (row < Nn) {
            float di = g_dinv[row];
            float d2 = di * di;
            float v[4];
            asm("mov.b64 {%0, %1}, %2;" : "=f"(v[0]), "=f"(v[1]) : "l"(acc[r][0]));
            asm("mov.b64 {%0, %1}, %2;" : "=f"(v[2]), "=f"(v[3]) : "l"(acc[r][1]));
            ((float4*)(hout + (size_t)row * Hh + tx * 4))[0] =
                make_float4(v[0], v[1], v[2], v[3]);
            ((float4*)(accout + (size_t)row * Hh + tx * 4))[0] =
                make_float4(v[0] * d2, v[1] * d2, v[2] * d2, v[3] * d2);
        }
    }
}

// ------------------------------------------------------------------
// Aggregation: warp per node, non-atomic, pipelined edge fetch. (R6-proven)
// ------------------------------------------------------------------
__global__ void agg_kernel(const float* __restrict__ h, const float* __restrict__ init,
                           float* __restrict__ out) {
    int warp = (blockIdx.x * blockDim.x + threadIdx.x) >> 5;
    int lane = threadIdx.x & 31;
    if (warp >= Nn) return;
    int beg = g_rowptr[warp], end = g_rowptr[warp + 1];
    float4 acc = ((const float4*)(init + (size_t)warp * Hh))[lane];
    int2 e = make_int2(0, 0);
    if (beg < end) e = g_csr[beg];
    for (int j = beg; j < end; j++) {
        int2 cur = e;
        if (j + 1 < end) e = g_csr[j + 1];
        float w = __int_as_float(cur.y);
        float4 v = ((const float4*)(h + (size_t)cur.x * Hh))[lane];
        acc.x = fmaf(w, v.x, acc.x);
        acc.y = fmaf(w, v.y, acc.y);
        acc.z = fmaf(w, v.z, acc.z);
        acc.w = fmaf(w, v.w, acc.w);
    }
    ((float4*)(out + (size_t)warp * Hh))[lane] = acc;
}

// ------------------------------------------------------------------
__device__ __forceinline__ int lower_bound_dev(const int* a, int n, int key) {
    int lo = 0, hi = n;
    while (lo < hi) {
        int mid = (lo + hi) >> 1;
        if (a[mid] < key) lo = mid + 1; else hi = mid;
    }
    return lo;
}

__global__ void pool_kernel(const int* __restrict__ batch, const float* __restrict__ acc,
                            const float* __restrict__ b3) {
    int g = blockIdx.x;
    int f = threadIdx.x;
    __shared__ int s_lo, s_hi;
    if (f == 0) s_lo = lower_bound_dev(batch, Nn, g);
    if (f == 1) s_hi = lower_bound_dev(batch, Nn, g + 1);
    __syncthreads();
    int lo = s_lo, hi = s_hi;
    float b = b3[f];
    float s0 = 0.f, s1 = 0.f, s2 = 0.f, s3 = 0.f;
    int n = lo;
    for (; n + 4 <= hi; n += 4) {
        s0 += fmaxf(acc[(size_t)(n + 0) * Hh + f] + b, 0.f);
        s1 += fmaxf(acc[(size_t)(n + 1) * Hh + f] + b, 0.f);
        s2 += fmaxf(acc[(size_t)(n + 2) * Hh + f] + b, 0.f);
        s3 += fmaxf(acc[(size_t)(n + 3) * Hh + f] + b, 0.f);
    }
    for (; n < hi; n++) s0 += fmaxf(acc[(size_t)n * Hh + f] + b, 0.f);
    float s = (s0 + s1) + (s2 + s3);
    g_pooled[g * Hh + f] = s / fmaxf((float)(hi - lo), 1.f);
}

__global__ void final_kernel(const float* __restrict__ Wl, const float* __restrict__ bl,
                             float* __restrict__ out) {
    int t = threadIdx.x;
    int g = t >> 1, c = t & 1;
    float s = 0.f;
#pragma unroll 8
    for (int k = 0; k < Hh; k++)
        s += g_pooled[g * Hh + k] * Wl[k * 2 + c];
    out[g * 2 + c] = s + bl[c];
}

// ------------------------------------------------------------------
extern "C" void kernel_launch(void* const* d_in, const int* in_sizes, int n_in,
                              void* d_out, int out_size) {
    const float* x     = (const float*)d_in[0];
    const int*   ei    = (const int*)d_in[1];
    const int*   batch = (const int*)d_in[2];
    const float* W1 = (const float*)d_in[3];
    const float* b1 = (const float*)d_in[4];
    const float* W2 = (const float*)d_in[5];
    const float* b2 = (const float*)d_in[6];
    const float* W3 = (const float*)d_in[7];
    const float* b3 = (const float*)d_in[8];
    const float* Wl = (const float*)d_in[9];
    const float* bl = (const float*)d_in[10];
    float* out = (float*)d_out;

    const int* src = ei;
    const int* dst = ei + Ee;

    float *hptr, *P, *Q;
    cudaGetSymbolAddress((void**)&hptr, g_h);
    cudaGetSymbolAddress((void**)&P, g_P);
    cudaGetSymbolAddress((void**)&Q, g_Q);

    const int SMEM = 2 * Hh * Hh * sizeof(float);   // 128 KB
    cudaFuncSetAttribute(gemm_kernel, cudaFuncAttributeMaxDynamicSharedMemorySize, SMEM);

    int gemm_blocks = (Nn + 127) / 128;              // 391
    int agg_blocks  = (Nn * 32 + 255) / 256;

    // #1..#3: minimal prefix so gemm1 is launch #4 (ncu captures #4)
    init_kernel<<<(Nn + 255) / 256, 256>>>();
    deg_kernel<<<(Ee + 255) / 256, 256>>>(dst);      // also writes ranks
    scanA_kernel<<<SCAN_B, SCAN_T>>>();              // block sums + dinv

    // #4: layer-1 GEMM (needs only dinv)
    gemm_kernel<<<gemm_blocks, 512, SMEM>>>(x, W1, nullptr, 0, hptr, P);

    // finish CSR build, then aggregate
    scanC_kernel<<<SCAN_B, SCAN_T>>>();
    fill_kernel<<<(Ee + 255) / 256, 256>>>(src, dst);
    agg_kernel<<<agg_blocks, 256>>>(hptr, P, Q);

    // Layer 2
    gemm_kernel<<<gemm_blocks, 512, SMEM>>>(Q, W2, b1, 1, hptr, P);
    agg_kernel<<<agg_blocks, 256>>>(hptr, P, Q);
    // Layer 3
    gemm_kernel<<<gemm_blocks, 512, SMEM>>>(Q, W3, b2, 1, hptr, P);
    agg_kernel<<<agg_blocks, 256>>>(hptr, P, Q);

    // Pool + head
    pool_kernel<<<Gg, Hh>>>(batch, Q, b3);
    final_kernel<<<1, 128>>>(Wl, bl, out);
}